// round 9
// baseline (speedup 1.0000x reference)
#include <cuda_runtime.h>

// ConvolutionalCapsule EM-routing. One CTA (512 threads) per position.
// Votes f32 in SMEM, votes_t[(o*16+p)*168 + 16*o + i]. Each R2-thread's work
// is split across two lanes (h) with near-zero combine cost:
//   M-step: (o,p,h) sweeps interleaved float4 chunks c=2r+h  -> 3 xor-1 SHFLs
//   E-step: (o,i_lo,h) handles r in {0..4} / {5..8}          -> no combine
// 204 KB smem, 1 CTA/SM, 16 warps/SM.

#define BATCH   8
#define HW      14
#define OHW     12
#define NPOS    (BATCH * OHW * OHW)   // 1152
#define NI      144
#define VSTR    168                   // floats per (o,p) row; VSTR/4 % 8 == 2
#define RSTR    152
#define CAP_EPS 1e-9f

#define VROWOFF(o, p) (((o)*16 + (p)) * VSTR + 16 * (o))

// SMEM layout (floats)
#define OFF_POSE (256*VSTR)               // 43008
#define OFF_RP   (OFF_POSE + 144*20)      // +2880
#define OFF_Z    (OFF_RP + 16*RSTR)       // +2432
#define OFF_A    (OFF_Z + NI*17)          // +2448
#define SMEM_FLOATS (OFF_A + NI)          // 50912
#define SMEM_BYTES  (SMEM_FLOATS * 4)     // 203648 B

__global__ __launch_bounds__(512, 1)
void capsule_em_kernel(const float* __restrict__ g_pose,
                       const float* __restrict__ g_act,
                       const float* __restrict__ g_w,
                       const float* __restrict__ g_bv,
                       const float* __restrict__ g_ba,
                       float* __restrict__ out)
{
    extern __shared__ float sm[];
    float* votes_t = sm;
    float* pose_sh = sm + OFF_POSE;   // [i*20 + 4*x + y]
    float* rp_sm   = sm + OFF_RP;     // rr' = rr * a, [o*152 + i]
    float* z_sm    = sm + OFF_Z;      // [i*17 + o]
    float* a_sh    = sm + OFF_A;      // [i]

    const int tid  = threadIdx.x;
    const int lane = tid & 31;
    const int o    = tid >> 5;        // warp = output capsule
    const int q    = lane >> 1;       // p (M-step) / i_lo (E-step) / i_c (votes)
    const int h    = lane & 1;        // half selector

    const int n   = blockIdx.x;
    const int b   = n / (OHW * OHW);
    const int rem = n - b * (OHW * OHW);
    const int h0  = rem / OHW;
    const int w0  = rem - h0 * OHW;

    // ---- Stage pose tile + activations ----
    {
        const float4* gp4 = (const float4*)g_pose;
        float4* ps4 = (float4*)pose_sh;
        #pragma unroll
        for (int idx = tid; idx < 576; idx += 512) {
            int kk = idx >> 6;
            int c4 = idx & 63;
            int di = kk / 3, dj = kk - di * 3;
            int pix = (b * HW + h0 + di) * HW + (w0 + dj);
            int cap = c4 >> 2, x = c4 & 3;
            ps4[(kk * 16 + cap) * 5 + x] = gp4[pix * 64 + c4];
        }
        if (tid < NI) {
            int kk = tid >> 4;
            int cap = tid & 15;
            int di = kk / 3, dj = kk - di * 3;
            int pix = (b * HW + h0 + di) * HW + (w0 + dj);
            a_sh[tid] = g_act[pix * 16 + cap];
        }
    }
    __syncthreads();

    // ---- rr' init + votes.  Thread (o, i_c=q, h) computes pose rows
    // x = 2h, 2h+1 -> vote elems p = 8h..8h+7 for i = q + 16j.
    for (int idx = tid; idx < 16 * NI; idx += 512) {
        int oo = idx / NI;
        int ii = idx - oo * NI;
        rp_sm[oo * RSTR + ii] = a_sh[ii] * 0.0625f;
    }
    {
        const float4* w4 = (const float4*)g_w;       // [i*64 + o*4 + y]
        const float4* p4 = (const float4*)pose_sh;   // [i*5 + x]
        #pragma unroll
        for (int j = 0; j < 9; j++) {
            int i = q + 16 * j;
            float4 pa  = p4[i * 5 + 2 * h];
            float4 pb  = p4[i * 5 + 2 * h + 1];
            float4 wr0 = w4[i * 64 + o * 4 + 0];
            float4 wr1 = w4[i * 64 + o * 4 + 1];
            float4 wr2 = w4[i * 64 + o * 4 + 2];
            float4 wr3 = w4[i * 64 + o * 4 + 3];
            float* vdst = votes_t + VROWOFF(o, 8 * h) + i;
            vdst[0*VSTR] = pa.x*wr0.x + pa.y*wr1.x + pa.z*wr2.x + pa.w*wr3.x;
            vdst[1*VSTR] = pa.x*wr0.y + pa.y*wr1.y + pa.z*wr2.y + pa.w*wr3.y;
            vdst[2*VSTR] = pa.x*wr0.z + pa.y*wr1.z + pa.z*wr2.z + pa.w*wr3.z;
            vdst[3*VSTR] = pa.x*wr0.w + pa.y*wr1.w + pa.z*wr2.w + pa.w*wr3.w;
            vdst[4*VSTR] = pb.x*wr0.x + pb.y*wr1.x + pb.z*wr2.x + pb.w*wr3.x;
            vdst[5*VSTR] = pb.x*wr0.y + pb.y*wr1.y + pb.z*wr2.y + pb.w*wr3.y;
            vdst[6*VSTR] = pb.x*wr0.z + pb.y*wr1.z + pb.z*wr2.z + pb.w*wr3.z;
            vdst[7*VSTR] = pb.x*wr0.w + pb.y*wr1.w + pb.z*wr2.w + pb.w*wr3.w;
        }
    }
    __syncthreads();

    // ---- EM routing ----
    const float bvo = g_bv[o];
    const float bao = g_ba[o];
    float mean = 0.0f, act = 0.0f;

    #pragma unroll 1
    for (int t = 0; t < 3; t++) {
        const float inv_temp = 1.0f + (float)t;

        // M-step: thread (o, p=q, h) sweeps float4 chunks c = 2r+h.
        float4 A0 = {0,0,0,0}, A1 = {0,0,0,0}, A2 = {0,0,0,0};
        {
            const float4* vr = (const float4*)(votes_t + VROWOFF(o, q)) + h;
            const float4* rr = (const float4*)(rp_sm + o * RSTR) + h;
            #pragma unroll
            for (int r = 0; r < 18; r++) {
                float4 v = vr[2*r];
                float4 s = rr[2*r];
                A0.x += s.x;                 A0.y += s.y;
                A0.z += s.z;                 A0.w += s.w;
                A1.x = fmaf(s.x, v.x, A1.x); A1.y = fmaf(s.y, v.y, A1.y);
                A1.z = fmaf(s.z, v.z, A1.z); A1.w = fmaf(s.w, v.w, A1.w);
                A2.x = fmaf(s.x * v.x, v.x, A2.x); A2.y = fmaf(s.y * v.y, v.y, A2.y);
                A2.z = fmaf(s.z * v.z, v.z, A2.z); A2.w = fmaf(s.w * v.w, v.w, A2.w);
            }
        }
        float S0 = (A0.x + A0.y) + (A0.z + A0.w);
        float S1 = (A1.x + A1.y) + (A1.z + A1.w);
        float S2 = (A2.x + A2.y) + (A2.z + A2.w);
        // combine the two halves (partner lane differs in bit 0)
        S0 += __shfl_xor_sync(0xffffffffu, S0, 1);
        S1 += __shfl_xor_sync(0xffffffffu, S1, 1);
        S2 += __shfl_xor_sync(0xffffffffu, S2, 1);

        float invS0 = __fdividef(1.0f, S0);
        mean = S1 * invS0;
        float var  = fmaxf(S2 * invS0 - mean * mean, 0.0f);
        float stdv = sqrtf(var);
        float lstd = __logf(stdv + CAP_EPS);

        // L = sum_p log(std+eps): butterfly over p (lane bits 1..4)
        float L = lstd;
        #pragma unroll
        for (int m = 2; m <= 16; m <<= 1) L += __shfl_xor_sync(0xffffffffu, L, m);

        float cost = S0 * (16.0f * bvo + L);
        act = 1.0f / (1.0f + __expf(-inv_temp * (bao - cost)));

        if (t < 2) {
            // E-step: thread (o, i_lo=q, h): r in {0..4} (h=0) / {5..8} (h=1)
            float iv = __fdividef(1.0f, 2.0f * var + CAP_EPS);
            float zc = __logf(act + CAP_EPS) - L;

            // gather mean/iv of all 16 p's for my o (independent shuffles)
            float mr[16], ir[16];
            #pragma unroll
            for (int pp = 0; pp < 16; pp++) {
                int src = (pp << 1) | h;
                mr[pp] = __shfl_sync(0xffffffffu, mean, src);
                ir[pp] = __shfl_sync(0xffffffffu, iv,   src);
            }

            const float* vbase = votes_t + VROWOFF(o, 0) + q;
            #pragma unroll
            for (int jj = 0; jj < 5; jj++) {
                int r = h ? (5 + jj) : jj;
                bool active = (jj < 4) || (h == 0);
                if (active) {
                    int ioff = 16 * r;
                    float s = 0.0f;
                    #pragma unroll
                    for (int pp = 0; pp < 16; pp++) {
                        float v = vbase[pp * VSTR + ioff];
                        float d = v - mr[pp];
                        s = fmaf(d * ir[pp], d, s);
                    }
                    z_sm[(q + ioff) * 17 + o] = zc - s;
                }
            }
            __syncthreads();

            // softmax over o per i, 288 threads: (i = tid>>1, oh = tid&1)
            if (tid < 2 * NI) {
                int i  = tid >> 1;
                int oh = tid & 1;
                float zr[8];
                float zmax = -1e30f;
                #pragma unroll
                for (int k = 0; k < 8; k++) {
                    zr[k] = z_sm[i * 17 + 8 * oh + k];
                    zmax = fmaxf(zmax, zr[k]);
                }
                zmax = fmaxf(zmax, __shfl_xor_sync(0xffffffffu, zmax, 1));
                float se = 0.0f;
                #pragma unroll
                for (int k = 0; k < 8; k++) {
                    zr[k] = __expf(zr[k] - zmax);
                    se += zr[k];
                }
                se += __shfl_xor_sync(0xffffffffu, se, 1);
                float scale = __fdividef(a_sh[i], se);
                #pragma unroll
                for (int k = 0; k < 8; k++)
                    rp_sm[(8 * oh + k) * RSTR + i] = zr[k] * scale;
            }
            __syncthreads();
        }
    }

    // ---- Outputs: pose [N,16,4,4] then activation [N,16] ----
    if (h == 0) {
        out[n * 256 + o * 16 + q] = mean;
        if (q == 0) out[NPOS * 256 + n * 16 + o] = act;
    }
}

extern "C" void kernel_launch(void* const* d_in, const int* in_sizes, int n_in,
                              void* d_out, int out_size)
{
    const float* g_pose = (const float*)d_in[0];
    const float* g_act  = (const float*)d_in[1];
    const float* g_w    = (const float*)d_in[2];
    const float* g_bv   = (const float*)d_in[3];
    const float* g_ba   = (const float*)d_in[4];
    float* out = (float*)d_out;

    cudaFuncSetAttribute(capsule_em_kernel,
                         cudaFuncAttributeMaxDynamicSharedMemorySize, SMEM_BYTES);
    capsule_em_kernel<<<NPOS, 512, SMEM_BYTES>>>(g_pose, g_act, g_w, g_bv, g_ba, out);
}

// round 10
// speedup vs baseline: 1.1730x; 1.1730x over previous
#include <cuda_runtime.h>

// ConvolutionalCapsule EM-routing, fully fused, one CTA (256 thr) per position.
// R5 structure (register-resident votes for M-steps) with the SMEM vote copy
// laid out [i][o*16+p] (rows of 260 floats) so the E-step reads float4 over p:
//   t=0 M-step : 144 conflict-free scalar LDS (loads + stashes into vreg)
//   t=1,2 M    : pure register FMA (+ broadcast rr float4)
//   E-step     : 4 LDS.128 per i (36 per E-step) instead of 144 scalar
//   vote write : 4 STS.128 per i

#define BATCH   8
#define HW      14
#define OHW     12
#define NPOS    (BATCH * OHW * OHW)   // 1152
#define NI      144
#define V2STR   260                   // floats per i-row in votes2
#define RSTR    152                   // floats per o in rr' (rp)
#define CAP_EPS 1e-9f

// SMEM layout (floats)
#define OFF_POSE (NI*V2STR)               // 37440
#define OFF_RP   (OFF_POSE + 144*20)      // +2880
#define OFF_Z    (OFF_RP + 16*RSTR)       // +2432
#define OFF_A    (OFF_Z + NI*17)          // +2448
#define SMEM_FLOATS (OFF_A + NI)          // 45344
#define SMEM_BYTES  (SMEM_FLOATS * 4)     // 181376 B < 227 KB, 1 CTA/SM

__global__ __launch_bounds__(256, 1)
void capsule_em_kernel(const float* __restrict__ g_pose,
                       const float* __restrict__ g_act,
                       const float* __restrict__ g_w,
                       const float* __restrict__ g_bv,
                       const float* __restrict__ g_ba,
                       float* __restrict__ out)
{
    extern __shared__ float sm[];
    float* votes2  = sm;              // [i*260 + o*16 + p]
    float* pose_sh = sm + OFF_POSE;   // [i*20 + 4*x + y]
    float* rp_sm   = sm + OFF_RP;     // rr' = rr * a, [o*152 + i]
    float* z_sm    = sm + OFF_Z;      // [i*17 + o]
    float* a_sh    = sm + OFF_A;      // [i]

    const int tid = threadIdx.x;
    const int n   = blockIdx.x;
    const int b   = n / (OHW * OHW);
    const int rem = n - b * (OHW * OHW);
    const int h0  = rem / OHW;
    const int w0  = rem - h0 * OHW;

    const int o = tid >> 4;   // output capsule
    const int p = tid & 15;   // pose elem (M) / i_lo (E) / i_c (votes)

    // ---- Stage pose tile + activations ----
    {
        const float4* gp4 = (const float4*)g_pose;
        float4* ps4 = (float4*)pose_sh;
        #pragma unroll
        for (int idx = tid; idx < 576; idx += 256) {
            int kk = idx >> 6;            // patch 0..8
            int c4 = idx & 63;            // cap*4 + x
            int di = kk / 3, dj = kk - di * 3;
            int pix = (b * HW + h0 + di) * HW + (w0 + dj);
            int cap = c4 >> 2, x = c4 & 3;
            ps4[(kk * 16 + cap) * 5 + x] = gp4[pix * 64 + c4];
        }
        if (tid < NI) {
            int kk = tid >> 4;
            int cap = tid & 15;
            int di = kk / 3, dj = kk - di * 3;
            int pix = (b * HW + h0 + di) * HW + (w0 + dj);
            a_sh[tid] = g_act[pix * 16 + cap];
        }
    }
    __syncthreads();

    // ---- Votes + rr' init.  votes[i][o][x][z] = sum_y pose[i][x][y]*w[i][o][y][z]
    // Thread (o, i_c=p) computes all 16 p-elems for i = p + 16j -> 4 STS.128.
    {
        const float4* w4 = (const float4*)g_w;       // [i*64 + o*4 + y]
        const float4* p4 = (const float4*)pose_sh;   // [i*5 + x]
        #pragma unroll
        for (int j = 0; j < 9; j++) {
            int i = p + 16 * j;
            float4 pr0 = p4[i * 5 + 0];
            float4 pr1 = p4[i * 5 + 1];
            float4 pr2 = p4[i * 5 + 2];
            float4 pr3 = p4[i * 5 + 3];
            float4 wr0 = w4[i * 64 + o * 4 + 0];
            float4 wr1 = w4[i * 64 + o * 4 + 1];
            float4 wr2 = w4[i * 64 + o * 4 + 2];
            float4 wr3 = w4[i * 64 + o * 4 + 3];
            float4* vdst = (float4*)(votes2 + i * V2STR + o * 16);
            #define VROW(PR, X) { float4 rrow;                                \
                rrow.x = PR.x*wr0.x + PR.y*wr1.x + PR.z*wr2.x + PR.w*wr3.x;   \
                rrow.y = PR.x*wr0.y + PR.y*wr1.y + PR.z*wr2.y + PR.w*wr3.y;   \
                rrow.z = PR.x*wr0.z + PR.y*wr1.z + PR.z*wr2.z + PR.w*wr3.z;   \
                rrow.w = PR.x*wr0.w + PR.y*wr1.w + PR.z*wr2.w + PR.w*wr3.w;   \
                vdst[X] = rrow; }
            VROW(pr0, 0)
            VROW(pr1, 1)
            VROW(pr2, 2)
            VROW(pr3, 3)
            #undef VROW
            rp_sm[o * RSTR + i] = a_sh[i] * 0.0625f;   // rr(1/16) * a
        }
    }
    __syncthreads();

    // ---- EM routing ----
    const float bvo = g_bv[o];
    const float bao = g_ba[o];
    float mean = 0.0f, act = 0.0f;

    float vreg[144];   // this thread's votes (i ascending), regs after t=0

    #pragma unroll 1
    for (int t = 0; t < 3; t++) {
        const float inv_temp = 1.0f + (float)t;

        // M-step: weighted moments over i for this (o,p)
        float4 A0 = {0,0,0,0}, A1 = {0,0,0,0}, A2 = {0,0,0,0};
        {
            const float4* rr = (const float4*)(rp_sm + o * RSTR);  // broadcast
            #define MACC1(K, VV, QQ) {                                        \
                A0.K += QQ; A1.K = fmaf(QQ, VV, A1.K);                        \
                A2.K = fmaf(QQ * VV, VV, A2.K); }
            if (t == 0) {
                const float* vp = votes2 + o * 16 + p;
                #pragma unroll
                for (int r = 0; r < 36; r++) {
                    float4 q = rr[r];
                    float v0 = vp[(4*r + 0) * V2STR];
                    float v1 = vp[(4*r + 1) * V2STR];
                    float v2 = vp[(4*r + 2) * V2STR];
                    float v3 = vp[(4*r + 3) * V2STR];
                    vreg[4*r + 0] = v0; vreg[4*r + 1] = v1;
                    vreg[4*r + 2] = v2; vreg[4*r + 3] = v3;
                    MACC1(x, v0, q.x) MACC1(y, v1, q.y)
                    MACC1(z, v2, q.z) MACC1(w, v3, q.w)
                }
            } else {
                #pragma unroll
                for (int r = 0; r < 36; r++) {
                    float4 q = rr[r];
                    MACC1(x, vreg[4*r + 0], q.x) MACC1(y, vreg[4*r + 1], q.y)
                    MACC1(z, vreg[4*r + 2], q.z) MACC1(w, vreg[4*r + 3], q.w)
                }
            }
            #undef MACC1
        }
        float S0 = (A0.x + A0.y) + (A0.z + A0.w);
        float S1 = (A1.x + A1.y) + (A1.z + A1.w);
        float S2 = (A2.x + A2.y) + (A2.z + A2.w);

        float invS0 = __fdividef(1.0f, S0);
        mean = S1 * invS0;
        float var  = fmaxf(S2 * invS0 - mean * mean, 0.0f);
        float stdv = sqrtf(var);
        float lstd = __logf(stdv + CAP_EPS);

        // L = sum_p log(std+eps): 16-lane butterfly
        float L = lstd;
        #pragma unroll
        for (int m = 8; m; m >>= 1) L += __shfl_xor_sync(0xffffffffu, L, m);

        float cost = S0 * (16.0f * bvo + L);
        act = 1.0f / (1.0f + __expf(-inv_temp * (bao - cost)));

        if (t < 2) {
            // E-step: thread (o, i_lo=p), 9 i values, float4 reads over p.
            float iv = __fdividef(1.0f, 2.0f * var + CAP_EPS);
            float zc = __logf(act + CAP_EPS) - L;

            // gather mean/iv of all 16 p-lanes for my o (independent shuffles)
            float mr[16], ir[16];
            const unsigned half_sel = (unsigned)(tid & 16);
            #pragma unroll
            for (int pp = 0; pp < 16; pp++) {
                mr[pp] = __shfl_sync(0xffffffffu, mean, half_sel | pp);
                ir[pp] = __shfl_sync(0xffffffffu, iv,   half_sel | pp);
            }

            #pragma unroll
            for (int r = 0; r < 9; r++) {
                int i = p + 16 * r;
                const float4* vp = (const float4*)(votes2 + i * V2STR + o * 16);
                float s = 0.0f;
                #pragma unroll
                for (int j = 0; j < 4; j++) {
                    float4 v = vp[j];
                    float d0 = v.x - mr[4*j + 0];
                    float d1 = v.y - mr[4*j + 1];
                    float d2 = v.z - mr[4*j + 2];
                    float d3 = v.w - mr[4*j + 3];
                    s = fmaf(d0 * ir[4*j + 0], d0, s);
                    s = fmaf(d1 * ir[4*j + 1], d1, s);
                    s = fmaf(d2 * ir[4*j + 2], d2, s);
                    s = fmaf(d3 * ir[4*j + 3], d3, s);
                }
                z_sm[i * 17 + o] = zc - s;
            }
            __syncthreads();

            // softmax over o per input capsule i; fold a into rr'
            if (tid < NI) {
                float zr[16];
                float zmax = -1e30f;
                #pragma unroll
                for (int oo = 0; oo < 16; oo++) {
                    zr[oo] = z_sm[tid * 17 + oo];
                    zmax = fmaxf(zmax, zr[oo]);
                }
                float se = 0.0f;
                #pragma unroll
                for (int oo = 0; oo < 16; oo++) {
                    zr[oo] = __expf(zr[oo] - zmax);
                    se += zr[oo];
                }
                float scale = __fdividef(a_sh[tid], se);
                #pragma unroll
                for (int oo = 0; oo < 16; oo++)
                    rp_sm[oo * RSTR + tid] = zr[oo] * scale;
            }
            __syncthreads();
        }
    }

    // ---- Outputs: pose [N,16,4,4] then activation [N,16] ----
    out[n * 256 + tid] = mean;
    if (p == 0) out[NPOS * 256 + n * 16 + o] = act;
}

extern "C" void kernel_launch(void* const* d_in, const int* in_sizes, int n_in,
                              void* d_out, int out_size)
{
    const float* g_pose = (const float*)d_in[0];
    const float* g_act  = (const float*)d_in[1];
    const float* g_w    = (const float*)d_in[2];
    const float* g_bv   = (const float*)d_in[3];
    const float* g_ba   = (const float*)d_in[4];
    float* out = (float*)d_out;

    cudaFuncSetAttribute(capsule_em_kernel,
                         cudaFuncAttributeMaxDynamicSharedMemorySize, SMEM_BYTES);
    capsule_em_kernel<<<NPOS, 256, SMEM_BYTES>>>(g_pose, g_act, g_w, g_bv, g_ba, out);
}

// round 12
// speedup vs baseline: 1.3762x; 1.1732x over previous
#include <cuda_runtime.h>

// ConvolutionalCapsule EM-routing, fully fused, one CTA (256 thr) per position.
// Votes NEVER touch SMEM: thread (o, c=i_lo) holds v[9][16] (all 16 pose elems
// of its 9 input capsules) in registers.
//  - t=0 M moments folded into the vote-compute loop (rr == a/16 constant).
//  - M-step per-p sums via 16-lane reduce-scatter (lane c ends with elem e=c).
//  - E-step distances all-register; 9 z STS per thread.
//  - softmax: 144 threads, one input capsule each (FIXED from R11's 288-thread
//    variant that silently skipped capsules 128..143 in a 256-thread block).
// SMEM: 31 KB (pose stage, rp, z, a).

#define BATCH   8
#define HW      14
#define OHW     12
#define NPOS    (BATCH * OHW * OHW)   // 1152
#define NI      144
#define RSTR    144                   // floats per o in rr'
#define CAP_EPS 1e-9f

// SMEM layout (floats)
#define OFF_RP   2880                 // pose: 144*20
#define OFF_Z    (OFF_RP + 16*RSTR)   // +2304
#define OFF_A    (OFF_Z + NI*17)      // +2448
#define SMEM_FLOATS (OFF_A + NI)      // 7776
#define SMEM_BYTES  (SMEM_FLOATS * 4) // 31104 B

// 16-lane reduce-scatter over lane bits 0..3: lane c ends with sum_lanes T[c].
#define SCATTER16(T) {                                                     \
    _Pragma("unroll")                                                      \
    for (int m_ = 8; m_ >= 1; m_ >>= 1) {                                  \
        const bool hi_ = (c & m_) != 0;                                    \
        _Pragma("unroll")                                                  \
        for (int k_ = 0; k_ < m_; k_++) {                                  \
            float send_ = hi_ ? T[k_] : T[k_ + m_];                        \
            float recv_ = __shfl_xor_sync(0xffffffffu, send_, m_);         \
            T[k_] = (hi_ ? T[k_ + m_] : T[k_]) + recv_;                    \
        }                                                                  \
    } }

__global__ __launch_bounds__(256, 1)
void capsule_em_kernel(const float* __restrict__ g_pose,
                       const float* __restrict__ g_act,
                       const float* __restrict__ g_w,
                       const float* __restrict__ g_bv,
                       const float* __restrict__ g_ba,
                       float* __restrict__ out)
{
    extern __shared__ float sm[];
    float* pose_sh = sm;              // [i*20 + 4*x + y]
    float* rp_sm   = sm + OFF_RP;     // rr' = rr * a, [o*144 + i]
    float* z_sm    = sm + OFF_Z;      // [i*17 + o]
    float* a_sh    = sm + OFF_A;      // [i]

    const int tid  = threadIdx.x;
    const int o    = tid >> 4;        // output capsule
    const int c    = tid & 15;        // i_lo; also ends up owning pose elem e=c
    const int half = tid & 16;        // which 16-lane half of the warp

    const int n   = blockIdx.x;
    const int b   = n / (OHW * OHW);
    const int rem = n - b * (OHW * OHW);
    const int h0  = rem / OHW;
    const int w0  = rem - h0 * OHW;

    // ---- Stage pose tile + activations ----
    {
        const float4* gp4 = (const float4*)g_pose;
        float4* ps4 = (float4*)pose_sh;
        #pragma unroll
        for (int idx = tid; idx < 576; idx += 256) {
            int kk = idx >> 6;            // patch 0..8
            int c4 = idx & 63;            // cap*4 + x
            int di = kk / 3, dj = kk - di * 3;
            int pix = (b * HW + h0 + di) * HW + (w0 + dj);
            int cap = c4 >> 2, x = c4 & 3;
            ps4[(kk * 16 + cap) * 5 + x] = gp4[pix * 64 + c4];
        }
        if (tid < NI) {
            int kk = tid >> 4;
            int cap = tid & 15;
            int di = kk / 3, dj = kk - di * 3;
            int pix = (b * HW + h0 + di) * HW + (w0 + dj);
            a_sh[tid] = g_act[pix * 16 + cap];
        }
    }
    __syncthreads();

    // ---- Votes into registers + t=0 moments in-flight ----
    // v[j*16 + 4x + z] = sum_y pose[i][x][y] * w[i][o][y][z], i = c + 16j.
    float v[144];
    float T0 = 0.0f, T1[16], T2[16];
    #pragma unroll
    for (int e = 0; e < 16; e++) { T1[e] = 0.0f; T2[e] = 0.0f; }
    {
        const float4* w4 = (const float4*)g_w;       // [i*64 + o*4 + y]
        const float4* p4 = (const float4*)pose_sh;   // [i*5 + x]
        #pragma unroll
        for (int j = 0; j < 9; j++) {
            int i = c + 16 * j;
            float ai = a_sh[i] * 0.0625f;            // rr(1/16) * a
            float4 pr0 = p4[i * 5 + 0];
            float4 pr1 = p4[i * 5 + 1];
            float4 pr2 = p4[i * 5 + 2];
            float4 pr3 = p4[i * 5 + 3];
            float4 wr0 = w4[i * 64 + o * 4 + 0];
            float4 wr1 = w4[i * 64 + o * 4 + 1];
            float4 wr2 = w4[i * 64 + o * 4 + 2];
            float4 wr3 = w4[i * 64 + o * 4 + 3];
            T0 += ai;
            #define VROW(PR, X) {                                           \
                float e0 = PR.x*wr0.x + PR.y*wr1.x + PR.z*wr2.x + PR.w*wr3.x; \
                float e1 = PR.x*wr0.y + PR.y*wr1.y + PR.z*wr2.y + PR.w*wr3.y; \
                float e2 = PR.x*wr0.z + PR.y*wr1.z + PR.z*wr2.z + PR.w*wr3.z; \
                float e3 = PR.x*wr0.w + PR.y*wr1.w + PR.z*wr2.w + PR.w*wr3.w; \
                v[j*16 + 4*(X) + 0] = e0;  v[j*16 + 4*(X) + 1] = e1;          \
                v[j*16 + 4*(X) + 2] = e2;  v[j*16 + 4*(X) + 3] = e3;          \
                T1[4*(X)+0] = fmaf(ai, e0, T1[4*(X)+0]);                      \
                T2[4*(X)+0] = fmaf(ai * e0, e0, T2[4*(X)+0]);                 \
                T1[4*(X)+1] = fmaf(ai, e1, T1[4*(X)+1]);                      \
                T2[4*(X)+1] = fmaf(ai * e1, e1, T2[4*(X)+1]);                 \
                T1[4*(X)+2] = fmaf(ai, e2, T1[4*(X)+2]);                      \
                T2[4*(X)+2] = fmaf(ai * e2, e2, T2[4*(X)+2]);                 \
                T1[4*(X)+3] = fmaf(ai, e3, T1[4*(X)+3]);                      \
                T2[4*(X)+3] = fmaf(ai * e3, e3, T2[4*(X)+3]); }
            VROW(pr0, 0)
            VROW(pr1, 1)
            VROW(pr2, 2)
            VROW(pr3, 3)
            #undef VROW
        }
    }

    // ---- EM routing ----
    const float bvo = g_bv[o];
    const float bao = g_ba[o];
    float mean = 0.0f, act = 0.0f;

    #pragma unroll 1
    for (int t = 0; t < 3; t++) {
        const float inv_temp = 1.0f + (float)t;

        if (t > 0) {
            // M-step t=1,2: accumulate moments from register votes
            T0 = 0.0f;
            #pragma unroll
            for (int e = 0; e < 16; e++) { T1[e] = 0.0f; T2[e] = 0.0f; }
            #pragma unroll
            for (int j = 0; j < 9; j++) {
                float q = rp_sm[o * RSTR + c + 16 * j];
                T0 += q;
                #pragma unroll
                for (int e = 0; e < 16; e++) {
                    float vv = v[j*16 + e];
                    T1[e] = fmaf(q, vv, T1[e]);
                    T2[e] = fmaf(q * vv, vv, T2[e]);
                }
            }
        }

        // S0: allreduce over the 16 i_lo lanes
        float S0 = T0;
        #pragma unroll
        for (int m = 8; m >= 1; m >>= 1)
            S0 += __shfl_xor_sync(0xffffffffu, S0, m);
        // S1/S2: reduce-scatter -> lane c owns pose element e = c
        SCATTER16(T1)
        SCATTER16(T2)
        float S1 = T1[0];
        float S2 = T2[0];

        float invS0 = __fdividef(1.0f, S0);
        mean = S1 * invS0;
        float var  = fmaxf(S2 * invS0 - mean * mean, 0.0f);
        float stdv = sqrtf(var);
        float lstd = __logf(stdv + CAP_EPS);

        // L = sum over the 16 pose elems (held one-per-lane)
        float L = lstd;
        #pragma unroll
        for (int m = 8; m >= 1; m >>= 1)
            L += __shfl_xor_sync(0xffffffffu, L, m);

        float cost = S0 * (16.0f * bvo + L);
        act = 1.0f / (1.0f + __expf(-inv_temp * (bao - cost)));

        if (t < 2) {
            // E-step: all-register distances for my 9 i's
            float iv = __fdividef(1.0f, 2.0f * var + CAP_EPS);
            float zc = __logf(act + CAP_EPS) - L;

            float mr[16], ir[16];
            #pragma unroll
            for (int e = 0; e < 16; e++) {
                mr[e] = __shfl_sync(0xffffffffu, mean, half | e);
                ir[e] = __shfl_sync(0xffffffffu, iv,   half | e);
            }

            #pragma unroll
            for (int j = 0; j < 9; j++) {
                float s = 0.0f;
                #pragma unroll
                for (int e = 0; e < 16; e++) {
                    float d = v[j*16 + e] - mr[e];
                    s = fmaf(d * ir[e], d, s);
                }
                z_sm[(c + 16 * j) * 17 + o] = zc - s;
            }
            __syncthreads();

            // softmax over o per input capsule i (144 threads, 16 o's each)
            if (tid < NI) {
                float zr[16];
                float zmax = -1e30f;
                #pragma unroll
                for (int oo = 0; oo < 16; oo++) {
                    zr[oo] = z_sm[tid * 17 + oo];
                    zmax = fmaxf(zmax, zr[oo]);
                }
                float se = 0.0f;
                #pragma unroll
                for (int oo = 0; oo < 16; oo++) {
                    zr[oo] = __expf(zr[oo] - zmax);
                    se += zr[oo];
                }
                float scale = __fdividef(a_sh[tid], se);
                #pragma unroll
                for (int oo = 0; oo < 16; oo++)
                    rp_sm[oo * RSTR + tid] = zr[oo] * scale;
            }
            __syncthreads();
        }
    }

    // ---- Outputs: pose [N,16,4,4] then activation [N,16] ----
    out[n * 256 + o * 16 + c] = mean;    // lane c owns pose element e=c
    if (c == 0) out[NPOS * 256 + n * 16 + o] = act;
}

extern "C" void kernel_launch(void* const* d_in, const int* in_sizes, int n_in,
                              void* d_out, int out_size)
{
    const float* g_pose = (const float*)d_in[0];
    const float* g_act  = (const float*)d_in[1];
    const float* g_w    = (const float*)d_in[2];
    const float* g_bv   = (const float*)d_in[3];
    const float* g_ba   = (const float*)d_in[4];
    float* out = (float*)d_out;

    cudaFuncSetAttribute(capsule_em_kernel,
                         cudaFuncAttributeMaxDynamicSharedMemorySize, SMEM_BYTES);
    capsule_em_kernel<<<NPOS, 256, SMEM_BYTES>>>(g_pose, g_act, g_w, g_bv, g_ba, out);
}